// round 1
// baseline (speedup 1.0000x reference)
#include <cuda_runtime.h>

// VIN network fused kernel:
//   phi   = obs @ W_phi.T + b_phi        [B,48]
//   V     = 20-step value iteration on 4x4 grid (rin=phi[0:16], rout=phi[16:32], p=phi[32:48])
//   logit = obs @ W_logit.T + b_logit    [B,5]
//   V_    = V[first nonzero of obs channel-1, else cell 5]
// Output layout assumed: out[0 : 5B] = logit row-major, out[5B : 6B] = V_.

#define KITERS 20

__global__ __launch_bounds__(256)
void vin_kernel(const float* __restrict__ obs,
                const float* __restrict__ Wphi,
                const float* __restrict__ bphi,
                const float* __restrict__ Wlog,
                const float* __restrict__ blog,
                float* __restrict__ out, int B)
{
    __shared__ __align__(16) float sW[48 * 48];
    __shared__ __align__(16) float sWl[5 * 48];
    __shared__ float sb[48];
    __shared__ float sbl[8];

    const int tid = threadIdx.x;
    for (int i = tid; i < 48 * 48; i += 256) sW[i] = Wphi[i];
    for (int i = tid; i < 5 * 48; i += 256) sWl[i] = Wlog[i];
    if (tid < 48) sb[tid] = bphi[tid];
    if (tid < 5)  sbl[tid] = blog[tid];
    __syncthreads();

    const int r = blockIdx.x * 256 + tid;
    if (r >= B) return;

    // ---- load obs row (16B vectorized, row stride 192B is 16B aligned) ----
    float o[48];
    const float4* op = reinterpret_cast<const float4*>(obs + (size_t)r * 48);
#pragma unroll
    for (int i = 0; i < 12; i++) {
        float4 t = op[i];
        o[4 * i + 0] = t.x; o[4 * i + 1] = t.y;
        o[4 * i + 2] = t.z; o[4 * i + 3] = t.w;
    }

    // ---- agent-position mask (channel 1 = obs[3c+1]), computed early ----
    unsigned mask = 0u;
#pragma unroll
    for (int c = 0; c < 16; c++)
        if (o[3 * c + 1] != 0.0f) mask |= (1u << c);

    // ---- phi = obs @ W_phi.T + b_phi  (4 accumulators for ILP, float4 weight loads) ----
    float phi[48];
#pragma unroll
    for (int j0 = 0; j0 < 48; j0 += 4) {
        float a0 = sb[j0 + 0], a1 = sb[j0 + 1], a2 = sb[j0 + 2], a3 = sb[j0 + 3];
#pragma unroll
        for (int k = 0; k < 48; k += 4) {
            float4 w0 = *reinterpret_cast<const float4*>(&sW[(j0 + 0) * 48 + k]);
            float4 w1 = *reinterpret_cast<const float4*>(&sW[(j0 + 1) * 48 + k]);
            float4 w2 = *reinterpret_cast<const float4*>(&sW[(j0 + 2) * 48 + k]);
            float4 w3 = *reinterpret_cast<const float4*>(&sW[(j0 + 3) * 48 + k]);
            a0 = fmaf(o[k + 0], w0.x, a0); a0 = fmaf(o[k + 1], w0.y, a0);
            a0 = fmaf(o[k + 2], w0.z, a0); a0 = fmaf(o[k + 3], w0.w, a0);
            a1 = fmaf(o[k + 0], w1.x, a1); a1 = fmaf(o[k + 1], w1.y, a1);
            a1 = fmaf(o[k + 2], w1.z, a1); a1 = fmaf(o[k + 3], w1.w, a1);
            a2 = fmaf(o[k + 0], w2.x, a2); a2 = fmaf(o[k + 1], w2.y, a2);
            a2 = fmaf(o[k + 2], w2.z, a2); a2 = fmaf(o[k + 3], w2.w, a2);
            a3 = fmaf(o[k + 0], w3.x, a3); a3 = fmaf(o[k + 1], w3.y, a3);
            a3 = fmaf(o[k + 2], w3.z, a3); a3 = fmaf(o[k + 3], w3.w, a3);
        }
        phi[j0 + 0] = a0; phi[j0 + 1] = a1; phi[j0 + 2] = a2; phi[j0 + 3] = a3;
    }

    // ---- logits, written out immediately ----
    {
        float a0 = sbl[0], a1 = sbl[1], a2 = sbl[2], a3 = sbl[3], a4 = sbl[4];
#pragma unroll
        for (int k = 0; k < 48; k += 4) {
            float4 w0 = *reinterpret_cast<const float4*>(&sWl[0 * 48 + k]);
            float4 w1 = *reinterpret_cast<const float4*>(&sWl[1 * 48 + k]);
            float4 w2 = *reinterpret_cast<const float4*>(&sWl[2 * 48 + k]);
            float4 w3 = *reinterpret_cast<const float4*>(&sWl[3 * 48 + k]);
            float4 w4 = *reinterpret_cast<const float4*>(&sWl[4 * 48 + k]);
            a0 = fmaf(o[k + 0], w0.x, a0); a0 = fmaf(o[k + 1], w0.y, a0);
            a0 = fmaf(o[k + 2], w0.z, a0); a0 = fmaf(o[k + 3], w0.w, a0);
            a1 = fmaf(o[k + 0], w1.x, a1); a1 = fmaf(o[k + 1], w1.y, a1);
            a1 = fmaf(o[k + 2], w1.z, a1); a1 = fmaf(o[k + 3], w1.w, a1);
            a2 = fmaf(o[k + 0], w2.x, a2); a2 = fmaf(o[k + 1], w2.y, a2);
            a2 = fmaf(o[k + 2], w2.z, a2); a2 = fmaf(o[k + 3], w2.w, a2);
            a3 = fmaf(o[k + 0], w3.x, a3); a3 = fmaf(o[k + 1], w3.y, a3);
            a3 = fmaf(o[k + 2], w3.z, a3); a3 = fmaf(o[k + 3], w3.w, a3);
            a4 = fmaf(o[k + 0], w4.x, a4); a4 = fmaf(o[k + 1], w4.y, a4);
            a4 = fmaf(o[k + 2], w4.z, a4); a4 = fmaf(o[k + 3], w4.w, a4);
        }
        float* lo = out + (size_t)r * 5;
        lo[0] = a0; lo[1] = a1; lo[2] = a2; lo[3] = a3; lo[4] = a4;
    }

    // ---- value iteration (rin = phi[0:16], rout = phi[16:32], p = phi[32:48]) ----
    const float NEG_INF = __int_as_float(0xff800000);
    float v[16];
#pragma unroll
    for (int c = 0; c < 16; c++) v[c] = 0.0f;

    for (int it = 0; it < KITERS; it++) {
        float nv[16];
#pragma unroll
        for (int i = 0; i < 4; i++) {
#pragma unroll
            for (int j = 0; j < 4; j++) {
                const int c = i * 4 + j;
                const float pc = phi[32 + c];
                // out-of-bounds neighbor contributes candidate p*0 + 0 = 0;
                // interior cells (all 4 neighbors valid) must NOT include 0.
                const bool oob = (i == 0) || (i == 3) || (j == 0) || (j == 3);
                float m = oob ? 0.0f : NEG_INF;
                if (i > 0) m = fmaxf(m, fmaf(pc, v[c - 4], phi[c - 4]));
                if (i < 3) m = fmaxf(m, fmaf(pc, v[c + 4], phi[c + 4]));
                if (j > 0) m = fmaxf(m, fmaf(pc, v[c - 1], phi[c - 1]));
                if (j < 3) m = fmaxf(m, fmaf(pc, v[c + 1], phi[c + 1]));
                nv[c] = fmaxf(v[c], m - phi[16 + c]);
            }
        }
#pragma unroll
        for (int c = 0; c < 16; c++) v[c] = nv[c];
    }

    // ---- select V at first nonzero channel-1 cell (default cell 5) ----
    float Vsel = v[5];
#pragma unroll
    for (int c = 15; c >= 0; c--)
        if (mask & (1u << c)) Vsel = v[c];

    out[(size_t)5 * B + r] = Vsel;
}

extern "C" void kernel_launch(void* const* d_in, const int* in_sizes, int n_in,
                              void* d_out, int out_size)
{
    const float* obs  = (const float*)d_in[0];
    const float* Wphi = (const float*)d_in[1];
    const float* bphi = (const float*)d_in[2];
    const float* Wlog = (const float*)d_in[3];
    const float* blog = (const float*)d_in[4];
    float* out = (float*)d_out;
    const int B = in_sizes[0] / 48;
    const int grid = (B + 255) / 256;
    vin_kernel<<<grid, 256>>>(obs, Wphi, bphi, Wlog, blog, out, B);
}